// round 4
// baseline (speedup 1.0000x reference)
#include <cuda_runtime.h>
#include <stdint.h>

#define FRAMES   320
#define T_DIM    20
#define HH       256
#define WW       256
#define HW       65536
#define WIN      7
#define OW       250
#define NBANDS   5
#define RBAND    50          // output rows per band
#define INROWS   56          // RBAND + WIN - 1, divisible by 7
#define NWARP    10
#define NTHREADS (NWARP * 32)
#define OUTW     26          // outputs per warp (32 - 6)
#define TOTAL_PIX 20000000.0 // 320 * 250 * 250

__device__ unsigned int g_dr_bits[T_DIM];
__device__ double g_acc;

// ---------------------------------------------------------------- init
__global__ void init_kernel() {
    int i = threadIdx.x;
    if (i < T_DIM) g_dr_bits[i] = 0u;
    if (i == 0)    g_acc = 0.0;
}

// ---------------------------------------------------------------- per-t max of Yt
// 1280 blocks: blk = (b*T + t)*4 + chunk; each block scans 16384 floats (float4).
__global__ __launch_bounds__(256) void max_kernel(const float* __restrict__ Yt) {
    int blk   = blockIdx.x;
    int chunk = blk & 3;
    int bt    = blk >> 2;            // b*T_DIM + t
    int t     = bt % T_DIM;

    const float4* p = reinterpret_cast<const float4*>(Yt + (size_t)bt * HW)
                      + chunk * 4096 + threadIdx.x;
    float m = 0.0f;
#pragma unroll
    for (int i = 0; i < 16; ++i) {
        float4 v = p[i * 256];
        m = fmaxf(m, fmaxf(fmaxf(v.x, v.y), fmaxf(v.z, v.w)));
    }
#pragma unroll
    for (int o = 16; o; o >>= 1)
        m = fmaxf(m, __shfl_xor_sync(0xffffffffu, m, o));

    __shared__ float sm[8];
    if ((threadIdx.x & 31) == 0) sm[threadIdx.x >> 5] = m;
    __syncthreads();
    if (threadIdx.x == 0) {
        float mm = sm[0];
#pragma unroll
        for (int i = 1; i < 8; ++i) mm = fmaxf(mm, sm[i]);
        atomicMax(&g_dr_bits[t], __float_as_uint(mm));  // all values >= 0
    }
}

// horizontal sum of 7 consecutive lanes' values via shuffle tree (sum8 - tail)
__device__ __forceinline__ float hsum7(float v) {
    float s = v + __shfl_down_sync(0xffffffffu, v, 1);   // 2-sum
    s = s + __shfl_down_sync(0xffffffffu, s, 2);         // 4-sum
    s = s + __shfl_down_sync(0xffffffffu, s, 4);         // 8-sum
    s = s - __shfl_down_sync(0xffffffffu, v, 7);         // 7-sum
    return s;
}

// ---------------------------------------------------------------- main SSIM
__global__ __launch_bounds__(NTHREADS) void ssim_kernel(const float* __restrict__ X,
                                                        const float* __restrict__ Y) {
    const int band  = blockIdx.x;        // 0..NBANDS-1
    const int frame = blockIdx.y;        // 0..FRAMES-1
    const int t     = frame % T_DIM;

    const int w = threadIdx.x >> 5;
    const int l = threadIdx.x & 31;
    const int col = w * OUTW + l;        // 0..265
    const bool loadok = (col < WW);
    const bool outok  = (l < OUTW) && (col < OW);

    const float dr = __uint_as_float(g_dr_bits[t]);
    float c1 = 0.01f * dr; c1 *= c1;
    float c2 = 0.03f * dr; c2 *= c2;

    const size_t base = (size_t)frame * HW + (size_t)(band * RBAND) * WW
                        + (loadok ? col : 0);
    const float* xp = X + base;
    const float* yp = Y + base;

    float sx = 0.f, sy = 0.f, sxx = 0.f, syy = 0.f, sxy = 0.f;
    float bx[WIN], by[WIN];
#pragma unroll
    for (int k = 0; k < WIN; ++k) { bx[k] = 0.f; by[k] = 0.f; }

    float acc = 0.f;

    for (int rr = 0; rr < INROWS; rr += WIN) {
#pragma unroll
        for (int k = 0; k < WIN; ++k) {
            const int r = rr + k;
            float x = loadok ? __ldg(xp + (size_t)r * WW) : 0.f;
            float y = loadok ? __ldg(yp + (size_t)r * WW) : 0.f;

            const float ox = bx[k], oy = by[k];
            sx += x - ox;
            sy += y - oy;
            sxx = fmaf(x, x, fmaf(-ox, ox, sxx));
            syy = fmaf(y, y, fmaf(-oy, oy, syy));
            sxy = fmaf(x, y, fmaf(-ox, oy, sxy));
            bx[k] = x; by[k] = y;

            if (r >= WIN - 1) {
                // horizontal 7-window sums (warp-uniform control flow here)
                const float hx  = hsum7(sx);
                const float hy  = hsum7(sy);
                const float hxx = hsum7(sxx);
                const float hyy = hsum7(syy);
                const float hxy = hsum7(sxy);
                if (outok) {
                    const float P  = hx * hy;
                    const float Q  = fmaf(hx, hx, hy * hy);
                    const float A1 = fmaf(P, 2.0f / 2401.0f, c1);
                    const float B1 = fmaf(Q, 1.0f / 2401.0f, c1);
                    const float A2 = fmaf(hxy, 1.0f / 24.0f,
                                          fmaf(P, -1.0f / 1176.0f, c2));
                    const float B2 = fmaf(hxx + hyy, 1.0f / 48.0f,
                                          fmaf(Q, -1.0f / 2352.0f, c2));
                    acc = fmaf(A1 * A2, __frcp_rn(B1 * B2), acc);
                }
            }
        }
    }

    // block reduction -> one double atomic per block
    float v = acc;
#pragma unroll
    for (int o = 16; o; o >>= 1)
        v += __shfl_xor_sync(0xffffffffu, v, o);

    __shared__ float wsum[NWARP];
    if (l == 0) wsum[w] = v;
    __syncthreads();
    if (threadIdx.x == 0) {
        float s = 0.f;
#pragma unroll
        for (int i = 0; i < NWARP; ++i) s += wsum[i];
        atomicAdd(&g_acc, (double)s);
    }
}

// ---------------------------------------------------------------- finalize
__global__ void fin_kernel(float* __restrict__ out) {
    out[0] = (float)(1.0 - g_acc / TOTAL_PIX);
}

// ---------------------------------------------------------------- launch
extern "C" void kernel_launch(void* const* d_in, const int* in_sizes, int n_in,
                              void* d_out, int out_size) {
    (void)in_sizes; (void)n_in; (void)out_size;
    const float* X = (const float*)d_in[0];
    const float* Y = (const float*)d_in[1];

    init_kernel<<<1, 32>>>();
    max_kernel<<<1280, 256>>>(Y);
    dim3 grid(NBANDS, FRAMES);
    ssim_kernel<<<grid, NTHREADS>>>(X, Y);
    fin_kernel<<<1, 1>>>((float*)d_out);
}

// round 5
// speedup vs baseline: 1.4039x; 1.4039x over previous
#include <cuda_runtime.h>
#include <stdint.h>

#define FRAMES   320
#define T_DIM    20
#define WW       256
#define HW       65536
#define WIN      7
#define OW       250
#define BANDS    10
#define ORPB     25          // output rows per band
#define IRPB     31          // input rows per band (ORPB + WIN - 1)
#define WPB      4           // warps per block
#define NWARPS   (FRAMES * BANDS)       // 3200
#define NBLK     (NWARPS / WPB)         // 800
#define TOTAL_PIX 20000000.0 // 320 * 250 * 250

__device__ unsigned int g_dr_bits[T_DIM];
__device__ double g_acc;
__device__ unsigned int g_done = 0;

// ---------------------------------------------------------------- init
__global__ void init_kernel() {
    int i = threadIdx.x;
    if (i < T_DIM) g_dr_bits[i] = 0u;
    if (i == 0)    g_acc = 0.0;
}

// ---------------------------------------------------------------- per-t max of Yt
// 1280 blocks: blk = (b*T + t)*4 + chunk; each block scans 16384 floats (float4).
__global__ __launch_bounds__(256) void max_kernel(const float* __restrict__ Yt) {
    int blk   = blockIdx.x;
    int chunk = blk & 3;
    int bt    = blk >> 2;            // b*T_DIM + t
    int t     = bt % T_DIM;

    const float4* p = reinterpret_cast<const float4*>(Yt + (size_t)bt * HW)
                      + chunk * 4096 + threadIdx.x;
    float m = 0.0f;
#pragma unroll
    for (int i = 0; i < 16; ++i) {
        float4 v = p[i * 256];
        m = fmaxf(m, fmaxf(fmaxf(v.x, v.y), fmaxf(v.z, v.w)));
    }
#pragma unroll
    for (int o = 16; o; o >>= 1)
        m = fmaxf(m, __shfl_xor_sync(0xffffffffu, m, o));

    __shared__ float sm[8];
    if ((threadIdx.x & 31) == 0) sm[threadIdx.x >> 5] = m;
    __syncthreads();
    if (threadIdx.x == 0) {
        float mm = sm[0];
#pragma unroll
        for (int i = 1; i < 8; ++i) mm = fmaxf(mm, sm[i]);
        atomicMax(&g_dr_bits[t], __float_as_uint(mm));  // all values >= 0
    }
}

// ---------------------------------------------------------------- horizontal 7-window
// Thread owns 8 consecutive columns (v[0..7]). Produces the 7-window sum
// starting at each of its 8 columns via local prefix sums + 6 shuffles.
__device__ __forceinline__ void hwin7(const float v[8], float o[8]) {
    const float p1 = v[0];
    const float p2 = p1 + v[1];
    const float p3 = p2 + v[2];
    const float p4 = p3 + v[3];
    const float p5 = p4 + v[4];
    const float p6 = p5 + v[5];
    const float p7 = p6 + v[6];
    const float p8 = p7 + v[7];
    const float n1 = __shfl_down_sync(0xffffffffu, p1, 1);
    const float n2 = __shfl_down_sync(0xffffffffu, p2, 1);
    const float n3 = __shfl_down_sync(0xffffffffu, p3, 1);
    const float n4 = __shfl_down_sync(0xffffffffu, p4, 1);
    const float n5 = __shfl_down_sync(0xffffffffu, p5, 1);
    const float n6 = __shfl_down_sync(0xffffffffu, p6, 1);
    o[0] = p7;
    o[1] = p8 - p1;
    o[2] = (p8 - p2) + n1;
    o[3] = (p8 - p3) + n2;
    o[4] = (p8 - p4) + n3;
    o[5] = (p8 - p5) + n4;
    o[6] = (p8 - p6) + n5;
    o[7] = v[7] + n6;
}

// ---------------------------------------------------------------- main SSIM
// One warp = one (frame, band): 31 input rows, 25 output rows, full 256-col width.
__global__ void __launch_bounds__(128, 4) ssim_kernel(const float* __restrict__ X,
                                                      const float* __restrict__ Y,
                                                      float* __restrict__ out) {
    const int warp = threadIdx.x >> 5;
    const int lane = threadIdx.x & 31;
    const int wg   = blockIdx.x * WPB + warp;   // 0..NWARPS-1
    const int frame = wg / BANDS;
    const int band  = wg % BANDS;
    const int t     = frame % T_DIM;

    const float dr = __uint_as_float(g_dr_bits[t]);
    float c1 = 0.01f * dr; c1 *= c1;
    float c2 = 0.03f * dr; c2 *= c2;

    const size_t fbase = (size_t)frame * HW + (size_t)(band * ORPB) * WW + (lane << 3);
    const float4* xp = reinterpret_cast<const float4*>(X + fbase);
    const float4* yp = reinterpret_cast<const float4*>(Y + fbase);

    float sx[8], sy[8], sq[8], sp[8];
#pragma unroll
    for (int j = 0; j < 8; ++j) { sx[j] = 0.f; sy[j] = 0.f; sq[j] = 0.f; sp[j] = 0.f; }

    float acc = 0.f;

    for (int r = 0; r < IRPB; ++r) {
        const float4 xa = xp[r * 64];       // row stride = 256 floats = 64 float4
        const float4 xb = xp[r * 64 + 1];
        const float4 ya = yp[r * 64];
        const float4 yb = yp[r * 64 + 1];
        const float nx[8] = {xa.x, xa.y, xa.z, xa.w, xb.x, xb.y, xb.z, xb.w};
        const float ny[8] = {ya.x, ya.y, ya.z, ya.w, yb.x, yb.y, yb.z, yb.w};

        float ox[8], oy[8];
        if (r >= WIN) {                      // re-load outgoing row (L1/L2 hit)
            const float4 xc = xp[(r - WIN) * 64];
            const float4 xd = xp[(r - WIN) * 64 + 1];
            const float4 yc = yp[(r - WIN) * 64];
            const float4 yd = yp[(r - WIN) * 64 + 1];
            ox[0]=xc.x; ox[1]=xc.y; ox[2]=xc.z; ox[3]=xc.w;
            ox[4]=xd.x; ox[5]=xd.y; ox[6]=xd.z; ox[7]=xd.w;
            oy[0]=yc.x; oy[1]=yc.y; oy[2]=yc.z; oy[3]=yc.w;
            oy[4]=yd.x; oy[5]=yd.y; oy[6]=yd.z; oy[7]=yd.w;
        } else {
#pragma unroll
            for (int j = 0; j < 8; ++j) { ox[j] = 0.f; oy[j] = 0.f; }
        }

#pragma unroll
        for (int j = 0; j < 8; ++j) {
            const float xn = nx[j], yn = ny[j], xo = ox[j], yo = oy[j];
            sx[j] += xn - xo;
            sy[j] += yn - yo;
            sq[j] = fmaf(xn, xn, fmaf(yn, yn, fmaf(-xo, xo, fmaf(-yo, yo, sq[j]))));
            sp[j] = fmaf(xn, yn, fmaf(-xo, yo, sp[j]));
        }

        if (r >= WIN - 1) {
            float hx[8], hy[8], hq[8], hp[8];
            hwin7(sx, hx);
            hwin7(sy, hy);
            hwin7(sq, hq);
            hwin7(sp, hp);
#pragma unroll
            for (int j = 0; j < 8; ++j) {
                const int col = (lane << 3) + j;
                if (col < OW) {
                    const float P  = hx[j] * hy[j];
                    const float Q  = fmaf(hx[j], hx[j], hy[j] * hy[j]);
                    const float A1 = fmaf(P, 2.0f / 2401.0f, c1);
                    const float B1 = fmaf(Q, 1.0f / 2401.0f, c1);
                    const float A2 = fmaf(hp[j], 1.0f / 24.0f,
                                          fmaf(P, -1.0f / 1176.0f, c2));
                    const float B2 = fmaf(hq[j], 1.0f / 48.0f,
                                          fmaf(Q, -1.0f / 2352.0f, c2));
                    acc += __fdividef(A1 * A2, B1 * B2);
                }
            }
        }
    }

    // block reduction -> one double atomic per block, last block finalizes
    float v = acc;
#pragma unroll
    for (int o = 16; o; o >>= 1)
        v += __shfl_xor_sync(0xffffffffu, v, o);

    __shared__ float wsum[WPB];
    if (lane == 0) wsum[warp] = v;
    __syncthreads();
    if (threadIdx.x == 0) {
        float s = 0.f;
#pragma unroll
        for (int i = 0; i < WPB; ++i) s += wsum[i];
        atomicAdd(&g_acc, (double)s);
        __threadfence();
        unsigned int tick = atomicAdd(&g_done, 1u);
        if (tick == NBLK - 1) {           // last block: finalize + reset counter
            g_done = 0u;
            __threadfence();
            double a = *((volatile double*)&g_acc);
            out[0] = (float)(1.0 - a / TOTAL_PIX);
        }
    }
}

// ---------------------------------------------------------------- launch
extern "C" void kernel_launch(void* const* d_in, const int* in_sizes, int n_in,
                              void* d_out, int out_size) {
    (void)in_sizes; (void)n_in; (void)out_size;
    const float* X = (const float*)d_in[0];
    const float* Y = (const float*)d_in[1];

    init_kernel<<<1, 32>>>();
    max_kernel<<<1280, 256>>>(Y);
    ssim_kernel<<<NBLK, WPB * 32>>>(X, Y, (float*)d_out);
}

// round 6
// speedup vs baseline: 1.6637x; 1.1850x over previous
#include <cuda_runtime.h>
#include <stdint.h>

#define FRAMES   320
#define T_DIM    20
#define WW       256
#define HW       65536
#define WIN      7
#define OW       250
#define BANDS    10
#define ORPB     25          // output rows per band
#define IRPB     31          // input rows per band (ORPB + WIN - 1)
#define WPB      4           // warps per block
#define NWARPS   (FRAMES * BANDS)       // 3200
#define NBLK     (NWARPS / WPB)         // 800
#define TOTAL_PIX 20000000.0 // 320 * 250 * 250

typedef unsigned long long ull;

__device__ float g_part[T_DIM * 64];   // per-(t, b*4+chunk) partial maxes
__device__ double g_acc;
__device__ unsigned int g_done;

// ---------------------------------------------------------------- f32x2 helpers
__device__ __forceinline__ ull FMA2(ull a, ull b, ull c) {
    ull d; asm("fma.rn.f32x2 %0,%1,%2,%3;" : "=l"(d) : "l"(a), "l"(b), "l"(c)); return d;
}
__device__ __forceinline__ ull ADD2(ull a, ull b) {
    ull d; asm("add.rn.f32x2 %0,%1,%2;" : "=l"(d) : "l"(a), "l"(b)); return d;
}
__device__ __forceinline__ ull MUL2(ull a, ull b) {
    ull d; asm("mul.rn.f32x2 %0,%1,%2;" : "=l"(d) : "l"(a), "l"(b)); return d;
}
#define NEG2(a) ((a) ^ 0x8000000080000000ULL)
__device__ __forceinline__ ull PACK2(float lo, float hi) {
    ull d; asm("mov.b64 %0, {%1,%2};" : "=l"(d) : "f"(lo), "f"(hi)); return d;
}
__device__ __forceinline__ float LO2(ull a) {
    float f; asm("{ .reg .f32 h; mov.b64 {%0, h}, %1; }" : "=f"(f) : "l"(a)); return f;
}
__device__ __forceinline__ float HI2(ull a) {
    float f; asm("{ .reg .f32 l; mov.b64 {l, %0}, %1; }" : "=f"(f) : "l"(a)); return f;
}
__device__ __forceinline__ ull REP2(float v) { return PACK2(v, v); }

// ---------------------------------------------------------------- per-t partial max of Yt
// 1280 blocks: blk = (b*T + t)*4 + chunk; each block scans 16384 floats (float4)
// and writes ONE partial max with a plain store (no global init required).
__global__ __launch_bounds__(256) void max_kernel(const float* __restrict__ Yt) {
    int blk   = blockIdx.x;
    int chunk = blk & 3;
    int bt    = blk >> 2;            // b*T_DIM + t
    int t     = bt % T_DIM;
    int b     = bt / T_DIM;

    const float4* p = reinterpret_cast<const float4*>(Yt + (size_t)bt * HW)
                      + chunk * 4096 + threadIdx.x;
    float m = 0.0f;
#pragma unroll
    for (int i = 0; i < 16; ++i) {
        float4 v = p[i * 256];
        m = fmaxf(m, fmaxf(fmaxf(v.x, v.y), fmaxf(v.z, v.w)));
    }
#pragma unroll
    for (int o = 16; o; o >>= 1)
        m = fmaxf(m, __shfl_xor_sync(0xffffffffu, m, o));

    __shared__ float sm[8];
    if ((threadIdx.x & 31) == 0) sm[threadIdx.x >> 5] = m;
    __syncthreads();
    if (threadIdx.x == 0) {
        float mm = sm[0];
#pragma unroll
        for (int i = 1; i < 8; ++i) mm = fmaxf(mm, sm[i]);
        g_part[t * 64 + b * 4 + chunk] = mm;   // plain store, deterministic
        if (blk == 0) { g_acc = 0.0; g_done = 0u; }
    }
}

// ---------------------------------------------------------------- horizontal 7-window
// s[4] = packed pairs for this thread's 8 columns; o[4] = packed 7-window sums
// starting at each of its 8 columns. 7 prefix adds + 6 shuffles + 12 combines.
__device__ __forceinline__ void hwin7p(const ull s[4], ull o[4]) {
    const float v0 = LO2(s[0]), v1 = HI2(s[0]), v2 = LO2(s[1]), v3 = HI2(s[1]);
    const float v4 = LO2(s[2]), v5 = HI2(s[2]), v6 = LO2(s[3]), v7 = HI2(s[3]);
    const float p1 = v0;
    const float p2 = p1 + v1;
    const float p3 = p2 + v2;
    const float p4 = p3 + v3;
    const float p5 = p4 + v4;
    const float p6 = p5 + v5;
    const float p7 = p6 + v6;
    const float p8 = p7 + v7;
    const float n1 = __shfl_down_sync(0xffffffffu, p1, 1);
    const float n2 = __shfl_down_sync(0xffffffffu, p2, 1);
    const float n3 = __shfl_down_sync(0xffffffffu, p3, 1);
    const float n4 = __shfl_down_sync(0xffffffffu, p4, 1);
    const float n5 = __shfl_down_sync(0xffffffffu, p5, 1);
    const float n6 = __shfl_down_sync(0xffffffffu, p6, 1);
    o[0] = PACK2(p7, p8 - p1);
    o[1] = PACK2((p8 - p2) + n1, (p8 - p3) + n2);
    o[2] = PACK2((p8 - p4) + n3, (p8 - p5) + n4);
    o[3] = PACK2((p8 - p6) + n5, v7 + n6);
}

// ---------------------------------------------------------------- main SSIM
// One warp = one (frame, band): 31 input rows, 25 output rows, 256 cols.
__global__ void __launch_bounds__(128, 4) ssim_kernel(const float* __restrict__ X,
                                                      const float* __restrict__ Y,
                                                      float* __restrict__ out) {
    const int warp = threadIdx.x >> 5;
    const int lane = threadIdx.x & 31;
    const int wg   = blockIdx.x * WPB + warp;   // 0..NWARPS-1
    const int frame = wg / BANDS;
    const int band  = wg % BANDS;
    const int t     = frame % T_DIM;

    // per-t data_range from the 64 partial maxes (all lanes end with dr)
    float dm = fmaxf(g_part[t * 64 + lane], g_part[t * 64 + 32 + lane]);
#pragma unroll
    for (int o = 16; o; o >>= 1)
        dm = fmaxf(dm, __shfl_xor_sync(0xffffffffu, dm, o));
    const float dr = dm;
    float c1 = 0.01f * dr; c1 *= c1;
    float c2 = 0.03f * dr; c2 *= c2;
    const ull c1p = REP2(c1), c2p = REP2(c2);
    const ull kA1 = REP2(2.0f / 2401.0f);
    const ull kB1 = REP2(1.0f / 2401.0f);
    const ull kPA = REP2(1.0f / 24.0f);
    const ull kPB = REP2(-1.0f / 1176.0f);
    const ull kQA = REP2(1.0f / 48.0f);
    const ull kQB = REP2(-1.0f / 2352.0f);

    const size_t fbase = (size_t)frame * HW + (size_t)(band * ORPB) * WW + (lane << 3);
    const double2* xp = reinterpret_cast<const double2*>(X + fbase);
    const double2* yp = reinterpret_cast<const double2*>(Y + fbase);

    ull sx[4], sy[4], sq[4], sp[4];
#pragma unroll
    for (int j = 0; j < 4; ++j) { sx[j] = 0ull; sy[j] = 0ull; sq[j] = 0ull; sp[j] = 0ull; }

    float acc = 0.f;
    const int colbase = lane << 3;

    for (int r = 0; r < IRPB; ++r) {
        const double2 xa = xp[r * 32];       // row stride = 256 floats = 32 double2
        const double2 xb = xp[r * 32 + 1];
        const double2 ya = yp[r * 32];
        const double2 yb = yp[r * 32 + 1];
        const ull nx[4] = { (ull)__double_as_longlong(xa.x), (ull)__double_as_longlong(xa.y),
                            (ull)__double_as_longlong(xb.x), (ull)__double_as_longlong(xb.y) };
        const ull ny[4] = { (ull)__double_as_longlong(ya.x), (ull)__double_as_longlong(ya.y),
                            (ull)__double_as_longlong(yb.x), (ull)__double_as_longlong(yb.y) };

        ull ox[4], oy[4];
        if (r >= WIN) {                      // re-load outgoing row (L1/L2 hit)
            const double2 xc = xp[(r - WIN) * 32];
            const double2 xd = xp[(r - WIN) * 32 + 1];
            const double2 yc = yp[(r - WIN) * 32];
            const double2 yd = yp[(r - WIN) * 32 + 1];
            ox[0] = (ull)__double_as_longlong(xc.x); ox[1] = (ull)__double_as_longlong(xc.y);
            ox[2] = (ull)__double_as_longlong(xd.x); ox[3] = (ull)__double_as_longlong(xd.y);
            oy[0] = (ull)__double_as_longlong(yc.x); oy[1] = (ull)__double_as_longlong(yc.y);
            oy[2] = (ull)__double_as_longlong(yd.x); oy[3] = (ull)__double_as_longlong(yd.y);
        } else {
#pragma unroll
            for (int j = 0; j < 4; ++j) { ox[j] = 0ull; oy[j] = 0ull; }
        }

#pragma unroll
        for (int j = 0; j < 4; ++j) {
            const ull nxo = NEG2(ox[j]);     // sign-bit XOR: ALU pipe
            const ull nyo = NEG2(oy[j]);
            sx[j] = ADD2(sx[j], ADD2(nx[j], nxo));
            sy[j] = ADD2(sy[j], ADD2(ny[j], nyo));
            sq[j] = FMA2(nx[j], nx[j], FMA2(ny[j], ny[j],
                    FMA2(nxo, ox[j], FMA2(nyo, oy[j], sq[j]))));
            sp[j] = FMA2(nx[j], ny[j], FMA2(nxo, oy[j], sp[j]));
        }

        if (r >= WIN - 1) {
            ull hx[4], hy[4], hq[4], hp[4];
            hwin7p(sx, hx);
            hwin7p(sy, hy);
            hwin7p(sq, hq);
            hwin7p(sp, hp);
#pragma unroll
            for (int j = 0; j < 4; ++j) {
                const ull P  = MUL2(hx[j], hy[j]);
                const ull Q  = FMA2(hx[j], hx[j], MUL2(hy[j], hy[j]));
                const ull A1 = FMA2(P, kA1, c1p);
                const ull B1 = FMA2(Q, kB1, c1p);
                const ull A2 = FMA2(hp[j], kPA, FMA2(P, kPB, c2p));
                const ull B2 = FMA2(hq[j], kQA, FMA2(Q, kQB, c2p));
                const ull num = MUL2(A1, A2);
                const ull den = MUL2(B1, B2);
                const int c0 = colbase + 2 * j;
                if (c0 < OW)     acc += __fdividef(LO2(num), LO2(den));
                if (c0 + 1 < OW) acc += __fdividef(HI2(num), HI2(den));
            }
        }
    }

    // block reduction -> one double atomic per block, last block finalizes
    float v = acc;
#pragma unroll
    for (int o = 16; o; o >>= 1)
        v += __shfl_xor_sync(0xffffffffu, v, o);

    __shared__ float wsum[WPB];
    if (lane == 0) wsum[warp] = v;
    __syncthreads();
    if (threadIdx.x == 0) {
        float s = 0.f;
#pragma unroll
        for (int i = 0; i < WPB; ++i) s += wsum[i];
        atomicAdd(&g_acc, (double)s);
        __threadfence();
        unsigned int tick = atomicAdd(&g_done, 1u);
        if (tick == NBLK - 1) {           // last block: finalize
            __threadfence();
            double a = *((volatile double*)&g_acc);
            out[0] = (float)(1.0 - a / TOTAL_PIX);
        }
    }
}

// ---------------------------------------------------------------- launch
extern "C" void kernel_launch(void* const* d_in, const int* in_sizes, int n_in,
                              void* d_out, int out_size) {
    (void)in_sizes; (void)n_in; (void)out_size;
    const float* X = (const float*)d_in[0];
    const float* Y = (const float*)d_in[1];

    max_kernel<<<1280, 256>>>(Y);
    ssim_kernel<<<NBLK, WPB * 32>>>(X, Y, (float*)d_out);
}

// round 7
// speedup vs baseline: 2.1051x; 1.2653x over previous
#include <cuda_runtime.h>
#include <stdint.h>

#define FRAMES   320
#define T_DIM    20
#define WW       256
#define HW       65536
#define WIN      7
#define OW       250
#define BANDS    10
#define ORPB     25          // output rows per band
#define IRPB     31          // input rows per band (ORPB + WIN - 1)
#define WPB      4           // warps per block
#define NWARPS   (FRAMES * BANDS)       // 3200
#define NBLK     (NWARPS / WPB)         // 800
#define TOTAL_PIX 20000000.0 // 320 * 250 * 250

typedef unsigned long long ull;

__device__ float g_part[T_DIM * 64];   // per-(t, b*4+chunk) partial maxes
__device__ double g_acc;
__device__ unsigned int g_done;

// ---------------------------------------------------------------- f32x2 helpers
__device__ __forceinline__ ull FMA2(ull a, ull b, ull c) {
    ull d; asm("fma.rn.f32x2 %0,%1,%2,%3;" : "=l"(d) : "l"(a), "l"(b), "l"(c)); return d;
}
__device__ __forceinline__ ull ADD2(ull a, ull b) {
    ull d; asm("add.rn.f32x2 %0,%1,%2;" : "=l"(d) : "l"(a), "l"(b)); return d;
}
__device__ __forceinline__ ull MUL2(ull a, ull b) {
    ull d; asm("mul.rn.f32x2 %0,%1,%2;" : "=l"(d) : "l"(a), "l"(b)); return d;
}
#define NEG2(a) ((a) ^ 0x8000000080000000ULL)
__device__ __forceinline__ ull PACK2(float lo, float hi) {
    ull d; asm("mov.b64 %0, {%1,%2};" : "=l"(d) : "f"(lo), "f"(hi)); return d;
}
__device__ __forceinline__ float LO2(ull a) {
    float f; asm("{ .reg .f32 h; mov.b64 {%0, h}, %1; }" : "=f"(f) : "l"(a)); return f;
}
__device__ __forceinline__ float HI2(ull a) {
    float f; asm("{ .reg .f32 l; mov.b64 {l, %0}, %1; }" : "=f"(f) : "l"(a)); return f;
}
__device__ __forceinline__ ull REP2(float v) { return PACK2(v, v); }

// ---------------------------------------------------------------- per-t partial max of Yt
__global__ __launch_bounds__(256) void max_kernel(const float* __restrict__ Yt) {
    int blk   = blockIdx.x;
    int chunk = blk & 3;
    int bt    = blk >> 2;            // b*T_DIM + t
    int t     = bt % T_DIM;
    int b     = bt / T_DIM;

    const float4* p = reinterpret_cast<const float4*>(Yt + (size_t)bt * HW)
                      + chunk * 4096 + threadIdx.x;
    float m = 0.0f;
#pragma unroll
    for (int i = 0; i < 16; ++i) {
        float4 v = p[i * 256];
        m = fmaxf(m, fmaxf(fmaxf(v.x, v.y), fmaxf(v.z, v.w)));
    }
#pragma unroll
    for (int o = 16; o; o >>= 1)
        m = fmaxf(m, __shfl_xor_sync(0xffffffffu, m, o));

    __shared__ float sm[8];
    if ((threadIdx.x & 31) == 0) sm[threadIdx.x >> 5] = m;
    __syncthreads();
    if (threadIdx.x == 0) {
        float mm = sm[0];
#pragma unroll
        for (int i = 1; i < 8; ++i) mm = fmaxf(mm, sm[i]);
        g_part[t * 64 + b * 4 + chunk] = mm;   // plain store, deterministic
        if (blk == 0) { g_acc = 0.0; g_done = 0u; }
    }
}

// ---------------------------------------------------------------- horizontal 7-window
// s[4] = packed pairs for this thread's 8 columns; o[4] = packed 7-window sums.
__device__ __forceinline__ void hwin7p(const ull s[4], ull o[4]) {
    const float v0 = LO2(s[0]), v1 = HI2(s[0]), v2 = LO2(s[1]), v3 = HI2(s[1]);
    const float v4 = LO2(s[2]), v5 = HI2(s[2]), v6 = LO2(s[3]), v7 = HI2(s[3]);
    const float p1 = v0;
    const float p2 = p1 + v1;
    const float p3 = p2 + v2;
    const float p4 = p3 + v3;
    const float p5 = p4 + v4;
    const float p6 = p5 + v5;
    const float p7 = p6 + v6;
    const float p8 = p7 + v7;
    const float n1 = __shfl_down_sync(0xffffffffu, p1, 1);
    const float n2 = __shfl_down_sync(0xffffffffu, p2, 1);
    const float n3 = __shfl_down_sync(0xffffffffu, p3, 1);
    const float n4 = __shfl_down_sync(0xffffffffu, p4, 1);
    const float n5 = __shfl_down_sync(0xffffffffu, p5, 1);
    const float n6 = __shfl_down_sync(0xffffffffu, p6, 1);
    o[0] = PACK2(p7, p8 - p1);
    o[1] = PACK2((p8 - p2) + n1, (p8 - p3) + n2);
    o[2] = PACK2((p8 - p4) + n3, (p8 - p5) + n4);
    o[3] = PACK2((p8 - p6) + n5, v7 + n6);
}

// ---------------------------------------------------------------- main SSIM
// One warp = one (frame, band). Rotated loop: loads issued first, previous
// output row's hwin+epilogue runs in their shadow, then vertical update.
__global__ void __launch_bounds__(128, 5) ssim_kernel(const float* __restrict__ X,
                                                      const float* __restrict__ Y,
                                                      float* __restrict__ out) {
    const int warp = threadIdx.x >> 5;
    const int lane = threadIdx.x & 31;
    const int wg   = blockIdx.x * WPB + warp;   // 0..NWARPS-1
    const int frame = wg / BANDS;
    const int band  = wg % BANDS;
    const int t     = frame % T_DIM;
    const bool full = (lane != 31);  // lane 31: only j==0 columns (248,249) valid

    // per-t data_range from the 64 partial maxes
    float dm = fmaxf(g_part[t * 64 + lane], g_part[t * 64 + 32 + lane]);
#pragma unroll
    for (int o = 16; o; o >>= 1)
        dm = fmaxf(dm, __shfl_xor_sync(0xffffffffu, dm, o));
    const float dr = dm;
    float c1 = 0.01f * dr; c1 *= c1;
    float c2 = 0.03f * dr; c2 *= c2;
    const ull c1p = REP2(c1), c2p = REP2(c2);
    const ull kA1 = REP2(2.0f / 2401.0f);
    const ull kB1 = REP2(1.0f / 2401.0f);
    const ull kPA = REP2(1.0f / 24.0f);
    const ull kPB = REP2(-1.0f / 1176.0f);
    const ull kQA = REP2(1.0f / 48.0f);
    const ull kQB = REP2(-1.0f / 2352.0f);

    const size_t fbase = (size_t)frame * HW + (size_t)(band * ORPB) * WW + (lane << 3);
    const double2* xp = reinterpret_cast<const double2*>(X + fbase);
    const double2* yp = reinterpret_cast<const double2*>(Y + fbase);

    ull sx[4], sy[4], sq[4], sp[4];
#pragma unroll
    for (int j = 0; j < 4; ++j) { sx[j] = 0ull; sy[j] = 0ull; sq[j] = 0ull; sp[j] = 0ull; }

    float acc = 0.f;   // accumulates (S - 1) per pixel

    // epilogue: hwin + SSIM math on current states (one output row)
    auto epilogue = [&]() {
        ull hx[4], hy[4], hq[4], hp[4];
        hwin7p(sx, hx);
        hwin7p(sy, hy);
        hwin7p(sq, hq);
        hwin7p(sp, hp);
#pragma unroll
        for (int j = 0; j < 4; ++j) {
            const ull P  = MUL2(hx[j], hy[j]);
            const ull Q  = FMA2(hx[j], hx[j], MUL2(hy[j], hy[j]));
            const ull A1 = FMA2(P, kA1, c1p);
            const ull B1 = FMA2(Q, kB1, c1p);
            const ull A2 = FMA2(hp[j], kPA, FMA2(P, kPB, c2p));
            const ull B2 = FMA2(hq[j], kQA, FMA2(Q, kQB, c2p));
            const ull den  = MUL2(B1, B2);
            const ull diff = FMA2(A1, A2, NEG2(den));   // num - den, single rounding
            const float contrib = __fdividef(LO2(diff), LO2(den))
                                + __fdividef(HI2(diff), HI2(den));
            if (j == 0)      acc += contrib;
            else if (full)   acc += contrib;
        }
    };

    // prologue: rows 0..6, no subtract, no output
#pragma unroll
    for (int r = 0; r < WIN; ++r) {
        const double2 xa = xp[r * 32];
        const double2 xb = xp[r * 32 + 1];
        const double2 ya = yp[r * 32];
        const double2 yb = yp[r * 32 + 1];
        const ull nx[4] = { (ull)__double_as_longlong(xa.x), (ull)__double_as_longlong(xa.y),
                            (ull)__double_as_longlong(xb.x), (ull)__double_as_longlong(xb.y) };
        const ull ny[4] = { (ull)__double_as_longlong(ya.x), (ull)__double_as_longlong(ya.y),
                            (ull)__double_as_longlong(yb.x), (ull)__double_as_longlong(yb.y) };
#pragma unroll
        for (int j = 0; j < 4; ++j) {
            sx[j] = ADD2(sx[j], nx[j]);
            sy[j] = ADD2(sy[j], ny[j]);
            sq[j] = FMA2(nx[j], nx[j], FMA2(ny[j], ny[j], sq[j]));
            sp[j] = FMA2(nx[j], ny[j], sp[j]);
        }
    }

    // steady loop: rows 7..30 (branch-free, loads shadowed by epilogue)
#pragma unroll 1
    for (int r = WIN; r < IRPB; ++r) {
        // issue all 8 loads first
        const double2 xa = xp[r * 32];
        const double2 xb = xp[r * 32 + 1];
        const double2 ya = yp[r * 32];
        const double2 yb = yp[r * 32 + 1];
        const double2 xc = xp[(r - WIN) * 32];
        const double2 xd = xp[(r - WIN) * 32 + 1];
        const double2 yc = yp[(r - WIN) * 32];
        const double2 yd = yp[(r - WIN) * 32 + 1];

        // previous output row computed in the loads' shadow
        epilogue();

        const ull nx[4] = { (ull)__double_as_longlong(xa.x), (ull)__double_as_longlong(xa.y),
                            (ull)__double_as_longlong(xb.x), (ull)__double_as_longlong(xb.y) };
        const ull ny[4] = { (ull)__double_as_longlong(ya.x), (ull)__double_as_longlong(ya.y),
                            (ull)__double_as_longlong(yb.x), (ull)__double_as_longlong(yb.y) };
        const ull ox[4] = { (ull)__double_as_longlong(xc.x), (ull)__double_as_longlong(xc.y),
                            (ull)__double_as_longlong(xd.x), (ull)__double_as_longlong(xd.y) };
        const ull oy[4] = { (ull)__double_as_longlong(yc.x), (ull)__double_as_longlong(yc.y),
                            (ull)__double_as_longlong(yd.x), (ull)__double_as_longlong(yd.y) };
#pragma unroll
        for (int j = 0; j < 4; ++j) {
            const ull nxo = NEG2(ox[j]);     // sign-bit XOR on ALU pipe
            const ull nyo = NEG2(oy[j]);
            sx[j] = ADD2(sx[j], ADD2(nx[j], nxo));
            sy[j] = ADD2(sy[j], ADD2(ny[j], nyo));
            sq[j] = FMA2(nx[j], nx[j], FMA2(ny[j], ny[j],
                    FMA2(nxo, ox[j], FMA2(nyo, oy[j], sq[j]))));
            sp[j] = FMA2(nx[j], ny[j], FMA2(nxo, oy[j], sp[j]));
        }
    }
    epilogue();   // last output row (24)

    // block reduction -> one double atomic per block, last block finalizes
    float v = acc;
#pragma unroll
    for (int o = 16; o; o >>= 1)
        v += __shfl_xor_sync(0xffffffffu, v, o);

    __shared__ float wsum[WPB];
    if (lane == 0) wsum[warp] = v;
    __syncthreads();
    if (threadIdx.x == 0) {
        float s = 0.f;
#pragma unroll
        for (int i = 0; i < WPB; ++i) s += wsum[i];
        atomicAdd(&g_acc, (double)s);
        __threadfence();
        unsigned int tick = atomicAdd(&g_done, 1u);
        if (tick == NBLK - 1) {           // last block: finalize
            __threadfence();
            double a = *((volatile double*)&g_acc);
            out[0] = (float)(-a / TOTAL_PIX);   // 1 - mean(S) = -mean(S-1)
        }
    }
}

// ---------------------------------------------------------------- launch
extern "C" void kernel_launch(void* const* d_in, const int* in_sizes, int n_in,
                              void* d_out, int out_size) {
    (void)in_sizes; (void)n_in; (void)out_size;
    const float* X = (const float*)d_in[0];
    const float* Y = (const float*)d_in[1];

    max_kernel<<<1280, 256>>>(Y);
    ssim_kernel<<<NBLK, WPB * 32>>>(X, Y, (float*)d_out);
}

// round 8
// speedup vs baseline: 2.1430x; 1.0180x over previous
#include <cuda_runtime.h>
#include <stdint.h>

#define FRAMES   320
#define T_DIM    20
#define WW       256
#define HW       65536
#define WIN      7
#define OW       250
#define BANDS    10
#define ORPB     25          // output rows per band
#define IRPB     31          // input rows per band (ORPB + WIN - 1)
#define WPB      4           // warps per block
#define NWARPS   (FRAMES * BANDS)       // 3200
#define NBLK     (NWARPS / WPB)         // 800
#define TOTAL_PIX 20000000.0 // 320 * 250 * 250

typedef unsigned long long ull;

__device__ float g_part[T_DIM * 64];   // per-(t, b*4+chunk) partial maxes
__device__ double g_acc;
__device__ unsigned int g_done;

// ---------------------------------------------------------------- f32x2 helpers
__device__ __forceinline__ ull FMA2(ull a, ull b, ull c) {
    ull d; asm("fma.rn.f32x2 %0,%1,%2,%3;" : "=l"(d) : "l"(a), "l"(b), "l"(c)); return d;
}
__device__ __forceinline__ ull ADD2(ull a, ull b) {
    ull d; asm("add.rn.f32x2 %0,%1,%2;" : "=l"(d) : "l"(a), "l"(b)); return d;
}
__device__ __forceinline__ ull MUL2(ull a, ull b) {
    ull d; asm("mul.rn.f32x2 %0,%1,%2;" : "=l"(d) : "l"(a), "l"(b)); return d;
}
#define NEG2(a) ((a) ^ 0x8000000080000000ULL)
__device__ __forceinline__ ull PACK2(float lo, float hi) {
    ull d; asm("mov.b64 %0, {%1,%2};" : "=l"(d) : "f"(lo), "f"(hi)); return d;
}
__device__ __forceinline__ float LO2(ull a) {
    float f; asm("{ .reg .f32 h; mov.b64 {%0, h}, %1; }" : "=f"(f) : "l"(a)); return f;
}
__device__ __forceinline__ float HI2(ull a) {
    float f; asm("{ .reg .f32 l; mov.b64 {l, %0}, %1; }" : "=f"(f) : "l"(a)); return f;
}
__device__ __forceinline__ ull REP2(float v) { return PACK2(v, v); }

// ---------------------------------------------------------------- per-t partial max of Yt
__global__ __launch_bounds__(256) void max_kernel(const float* __restrict__ Yt) {
    int blk   = blockIdx.x;
    int chunk = blk & 3;
    int bt    = blk >> 2;            // b*T_DIM + t
    int t     = bt % T_DIM;
    int b     = bt / T_DIM;

    const float4* p = reinterpret_cast<const float4*>(Yt + (size_t)bt * HW)
                      + chunk * 4096 + threadIdx.x;
    float m = 0.0f;
#pragma unroll
    for (int i = 0; i < 16; ++i) {
        float4 v = p[i * 256];
        m = fmaxf(m, fmaxf(fmaxf(v.x, v.y), fmaxf(v.z, v.w)));
    }
#pragma unroll
    for (int o = 16; o; o >>= 1)
        m = fmaxf(m, __shfl_xor_sync(0xffffffffu, m, o));

    __shared__ float sm[8];
    if ((threadIdx.x & 31) == 0) sm[threadIdx.x >> 5] = m;
    __syncthreads();
    if (threadIdx.x == 0) {
        float mm = sm[0];
#pragma unroll
        for (int i = 1; i < 8; ++i) mm = fmaxf(mm, sm[i]);
        g_part[t * 64 + b * 4 + chunk] = mm;   // plain store, deterministic
        if (blk == 0) { g_acc = 0.0; g_done = 0u; }
    }
}

// ---------------------------------------------------------------- horizontal 7-window
__device__ __forceinline__ void hwin7p(const ull s[4], ull o[4]) {
    const float v0 = LO2(s[0]), v1 = HI2(s[0]), v2 = LO2(s[1]), v3 = HI2(s[1]);
    const float v4 = LO2(s[2]), v5 = HI2(s[2]), v6 = LO2(s[3]), v7 = HI2(s[3]);
    const float p1 = v0;
    const float p2 = p1 + v1;
    const float p3 = p2 + v2;
    const float p4 = p3 + v3;
    const float p5 = p4 + v4;
    const float p6 = p5 + v5;
    const float p7 = p6 + v6;
    const float p8 = p7 + v7;
    const float n1 = __shfl_down_sync(0xffffffffu, p1, 1);
    const float n2 = __shfl_down_sync(0xffffffffu, p2, 1);
    const float n3 = __shfl_down_sync(0xffffffffu, p3, 1);
    const float n4 = __shfl_down_sync(0xffffffffu, p4, 1);
    const float n5 = __shfl_down_sync(0xffffffffu, p5, 1);
    const float n6 = __shfl_down_sync(0xffffffffu, p6, 1);
    o[0] = PACK2(p7, p8 - p1);
    o[1] = PACK2((p8 - p2) + n1, (p8 - p3) + n2);
    o[2] = PACK2((p8 - p4) + n3, (p8 - p5) + n4);
    o[3] = PACK2((p8 - p6) + n5, v7 + n6);
}

// ---------------------------------------------------------------- main SSIM
// One warp = one (frame, band). Rotated loop; epilogue staged to minimize
// peak register liveness (hx/hy folded into P,Q before hp/hq are produced).
__global__ void __launch_bounds__(128, 6) ssim_kernel(const float* __restrict__ X,
                                                      const float* __restrict__ Y,
                                                      float* __restrict__ out) {
    const int warp = threadIdx.x >> 5;
    const int lane = threadIdx.x & 31;
    const int wg   = blockIdx.x * WPB + warp;   // 0..NWARPS-1
    const int frame = wg / BANDS;
    const int band  = wg % BANDS;
    const int t     = frame % T_DIM;
    const bool full = (lane != 31);  // lane 31: only j==0 columns (248,249) valid

    // per-t data_range from the 64 partial maxes
    float dm = fmaxf(g_part[t * 64 + lane], g_part[t * 64 + 32 + lane]);
#pragma unroll
    for (int o = 16; o; o >>= 1)
        dm = fmaxf(dm, __shfl_xor_sync(0xffffffffu, dm, o));
    const float dr = dm;
    float c1 = 0.01f * dr; c1 *= c1;
    float c2 = 0.03f * dr; c2 *= c2;
    const ull c1p = REP2(c1), c2p = REP2(c2);
    const ull kA1 = REP2(2.0f / 2401.0f);
    const ull kB1 = REP2(1.0f / 2401.0f);
    const ull kPA = REP2(1.0f / 24.0f);
    const ull kPB = REP2(-1.0f / 1176.0f);
    const ull kQA = REP2(1.0f / 48.0f);
    const ull kQB = REP2(-1.0f / 2352.0f);

    const size_t fbase = (size_t)frame * HW + (size_t)(band * ORPB) * WW + (lane << 3);
    const double2* xp = reinterpret_cast<const double2*>(X + fbase);
    const double2* yp = reinterpret_cast<const double2*>(Y + fbase);

    ull sx[4], sy[4], sq[4], sp[4];
#pragma unroll
    for (int j = 0; j < 4; ++j) { sx[j] = 0ull; sy[j] = 0ull; sq[j] = 0ull; sp[j] = 0ull; }

    float acc = 0.f;   // accumulates (S - 1) per pixel

    // epilogue: staged for low register liveness
    auto epilogue = [&]() {
        ull P[4], Q[4];
        {   // hx, hy live only in this scope
            ull hx[4], hy[4];
            hwin7p(sx, hx);
            hwin7p(sy, hy);
#pragma unroll
            for (int j = 0; j < 4; ++j) {
                P[j] = MUL2(hx[j], hy[j]);
                Q[j] = FMA2(hx[j], hx[j], MUL2(hy[j], hy[j]));
            }
        }
        ull A2[4];
        {   // hp live only here
            ull hp[4];
            hwin7p(sp, hp);
#pragma unroll
            for (int j = 0; j < 4; ++j)
                A2[j] = FMA2(hp[j], kPA, FMA2(P[j], kPB, c2p));
        }
        ull B2[4];
        {   // hq live only here
            ull hq[4];
            hwin7p(sq, hq);
#pragma unroll
            for (int j = 0; j < 4; ++j)
                B2[j] = FMA2(hq[j], kQA, FMA2(Q[j], kQB, c2p));
        }
#pragma unroll
        for (int j = 0; j < 4; ++j) {
            const ull A1 = FMA2(P[j], kA1, c1p);
            const ull B1 = FMA2(Q[j], kB1, c1p);
            const ull den  = MUL2(B1, B2[j]);
            const ull diff = FMA2(A1, A2[j], NEG2(den));   // num - den
            const float contrib = __fdividef(LO2(diff), LO2(den))
                                + __fdividef(HI2(diff), HI2(den));
            if (j == 0)      acc += contrib;
            else if (full)   acc += contrib;
        }
    };

    // prologue: rows 0..6, no subtract, no output
#pragma unroll
    for (int r = 0; r < WIN; ++r) {
        const double2 xa = xp[r * 32];
        const double2 xb = xp[r * 32 + 1];
        const double2 ya = yp[r * 32];
        const double2 yb = yp[r * 32 + 1];
        const ull nx[4] = { (ull)__double_as_longlong(xa.x), (ull)__double_as_longlong(xa.y),
                            (ull)__double_as_longlong(xb.x), (ull)__double_as_longlong(xb.y) };
        const ull ny[4] = { (ull)__double_as_longlong(ya.x), (ull)__double_as_longlong(ya.y),
                            (ull)__double_as_longlong(yb.x), (ull)__double_as_longlong(yb.y) };
#pragma unroll
        for (int j = 0; j < 4; ++j) {
            sx[j] = ADD2(sx[j], nx[j]);
            sy[j] = ADD2(sy[j], ny[j]);
            sq[j] = FMA2(nx[j], nx[j], FMA2(ny[j], ny[j], sq[j]));
            sp[j] = FMA2(nx[j], ny[j], sp[j]);
        }
    }

    // steady loop: rows 7..30 (loads shadowed by previous row's epilogue)
#pragma unroll 1
    for (int r = WIN; r < IRPB; ++r) {
        const double2 xa = xp[r * 32];
        const double2 xb = xp[r * 32 + 1];
        const double2 ya = yp[r * 32];
        const double2 yb = yp[r * 32 + 1];
        const double2 xc = xp[(r - WIN) * 32];
        const double2 xd = xp[(r - WIN) * 32 + 1];
        const double2 yc = yp[(r - WIN) * 32];
        const double2 yd = yp[(r - WIN) * 32 + 1];

        epilogue();   // previous output row, in the loads' shadow

        const ull nx[4] = { (ull)__double_as_longlong(xa.x), (ull)__double_as_longlong(xa.y),
                            (ull)__double_as_longlong(xb.x), (ull)__double_as_longlong(xb.y) };
        const ull ny[4] = { (ull)__double_as_longlong(ya.x), (ull)__double_as_longlong(ya.y),
                            (ull)__double_as_longlong(yb.x), (ull)__double_as_longlong(yb.y) };
        const ull ox[4] = { (ull)__double_as_longlong(xc.x), (ull)__double_as_longlong(xc.y),
                            (ull)__double_as_longlong(xd.x), (ull)__double_as_longlong(xd.y) };
        const ull oy[4] = { (ull)__double_as_longlong(yc.x), (ull)__double_as_longlong(yc.y),
                            (ull)__double_as_longlong(yd.x), (ull)__double_as_longlong(yd.y) };
#pragma unroll
        for (int j = 0; j < 4; ++j) {
            const ull nxo = NEG2(ox[j]);     // sign-bit XOR on ALU pipe
            const ull nyo = NEG2(oy[j]);
            sx[j] = ADD2(sx[j], ADD2(nx[j], nxo));
            sy[j] = ADD2(sy[j], ADD2(ny[j], nyo));
            sq[j] = FMA2(nx[j], nx[j], FMA2(ny[j], ny[j],
                    FMA2(nxo, ox[j], FMA2(nyo, oy[j], sq[j]))));
            sp[j] = FMA2(nx[j], ny[j], FMA2(nxo, oy[j], sp[j]));
        }
    }
    epilogue();   // last output row (24)

    // block reduction -> one double atomic per block, last block finalizes
    float v = acc;
#pragma unroll
    for (int o = 16; o; o >>= 1)
        v += __shfl_xor_sync(0xffffffffu, v, o);

    __shared__ float wsum[WPB];
    if (lane == 0) wsum[warp] = v;
    __syncthreads();
    if (threadIdx.x == 0) {
        float s = 0.f;
#pragma unroll
        for (int i = 0; i < WPB; ++i) s += wsum[i];
        atomicAdd(&g_acc, (double)s);
        __threadfence();
        unsigned int tick = atomicAdd(&g_done, 1u);
        if (tick == NBLK - 1) {           // last block: finalize
            __threadfence();
            double a = *((volatile double*)&g_acc);
            out[0] = (float)(-a / TOTAL_PIX);   // 1 - mean(S) = -mean(S-1)
        }
    }
}

// ---------------------------------------------------------------- launch
extern "C" void kernel_launch(void* const* d_in, const int* in_sizes, int n_in,
                              void* d_out, int out_size) {
    (void)in_sizes; (void)n_in; (void)out_size;
    const float* X = (const float*)d_in[0];
    const float* Y = (const float*)d_in[1];

    max_kernel<<<1280, 256>>>(Y);
    ssim_kernel<<<NBLK, WPB * 32>>>(X, Y, (float*)d_out);
}